// round 2
// baseline (speedup 1.0000x reference)
#include <cuda_runtime.h>
#include <cuda_bf16.h>

// ---------------- problem constants ----------------
#define B_    64
#define L_    512
#define G_    128
#define N_    32
#define K_    8
#define E_    65536
#define DTOK  64
#define H_    64
#define NINP  32
#define NRH   256          // NREL*NHID = 16*16
#define NA    2048         // B*N

// ---------------- scratch (__device__ globals; no allocation) ----------------
__device__ float g_xgrp[B_*G_*DTOK];        // (B,G,64)
__device__ float g_hgrp[B_*G_*2*H_];        // (B,G,128)  fwd[0:64) bwd[64:128)
__device__ float g_rawS[NA*NINP];
__device__ float g_rawD[NA*NINP];
__device__ float g_hsT [NA*NINP];
__device__ float g_htT [NA*NINP];
__device__ int   g_cntU[NA];
__device__ int   g_cntV[NA];
__device__ int   g_start[NA+1];
__device__ int   g_cursor[NA];
__device__ int   g_perm[E_];
__device__ float g_bnMu[64];
__device__ float g_bnInv[64];
__device__ float g_Ap[(size_t)NA*NRH*32];   // 64 MB
__device__ float g_C [NA*NRH];
__device__ float g_zsum[NRH];
__device__ float g_zsq [NRH];
__device__ float g_zscale[NRH];
__device__ float g_zoff  [NRH];
__device__ float g_z[(size_t)E_*NRH];       // 64 MB, layout (E, 256)

// ---------------- math helpers ----------------
__device__ __forceinline__ float sigp(float x) {            // precise-ish sigmoid
    return __fdividef(1.0f, 1.0f + __expf(-x));
}
__device__ __forceinline__ float tanhp(float x) {           // precise-ish tanh
    return 2.0f * sigp(2.0f * x) - 1.0f;
}
__device__ __forceinline__ float tanha(float x) {           // MUFU.TANH
    float y; asm("tanh.approx.f32 %0, %1;" : "=f"(y) : "f"(x)); return y;
}

// ---------------- 1: zero counters ----------------
__global__ void k_init() {
    int t = blockIdx.x * 256 + threadIdx.x;
    if (t < NA)  { g_cntU[t] = 0; g_cntV[t] = 0; }
    if (t < NRH) { g_zsum[t] = 0.f; g_zsq[t] = 0.f; }
}

// ---------------- 2: token embed + scatter-sum into groups (one CTA per b) ----
__global__ void k_embed(const int* __restrict__ seq, const int* __restrict__ p2g,
                        const float* __restrict__ emb) {
    __shared__ float acc[G_ * DTOK];          // 32 KB
    int b = blockIdx.x;
    int tid = threadIdx.x;                    // 256
    for (int i = tid; i < G_ * DTOK; i += 256) acc[i] = 0.f;
    __syncthreads();
    int sub  = tid & 15;                      // 16 threads per token (float4 each)
    int tok0 = tid >> 4;
    for (int l = tok0; l < L_; l += 16) {
        int s = seq[b * L_ + l];
        int g = p2g[b * L_ + l];
        float4 v = ((const float4*)(emb + (size_t)s * DTOK))[sub];
        float* dst = acc + g * DTOK + sub * 4;
        atomicAdd(dst + 0, v.x); atomicAdd(dst + 1, v.y);
        atomicAdd(dst + 2, v.z); atomicAdd(dst + 3, v.w);
    }
    __syncthreads();
    for (int i = tid; i < G_ * DTOK; i += 256) g_xgrp[b * G_ * DTOK + i] = acc[i];
}

// ---------------- 3: edge-endpoint histograms ----------------
__global__ void k_histo(const int* __restrict__ u, const int* __restrict__ v) {
    int e = blockIdx.x * 256 + threadIdx.x;
    atomicAdd(&g_cntU[u[e]], 1);
    atomicAdd(&g_cntV[v[e]], 1);
}

// ---------------- 4: BiLSTM. 128 CTAs = (b, dir), 256 threads = gate rows ----
__global__ void __launch_bounds__(256, 1)
k_lstm(const float* __restrict__ wihF, const float* __restrict__ whhF,
       const float* __restrict__ bihF, const float* __restrict__ bhhF,
       const float* __restrict__ wihB, const float* __restrict__ whhB,
       const float* __restrict__ bihB, const float* __restrict__ bhhB) {
    int b   = blockIdx.x & 63;
    int dir = blockIdx.x >> 6;
    const float* wih = dir ? wihB : wihF;
    const float* whh = dir ? whhB : whhF;
    const float* bih = dir ? bihB : bihF;
    const float* bhh = dir ? bhhB : bhhF;
    int j = threadIdx.x;                       // gate row 0..255 (i,f,g,o x 64)

    float4 wi[16], wh[16];
    #pragma unroll
    for (int q = 0; q < 16; q++) {
        wi[q] = ((const float4*)(wih + j * 64))[q];
        wh[q] = ((const float4*)(whh + j * 64))[q];
    }
    float bias = bih[j] + bhh[j];

    __shared__ float4 xs[16];                  // current x_t (64 f)
    __shared__ float4 hs[16];                  // current h (64 f)
    __shared__ float  gsm[256];
    float c = 0.f;

    if (j < 16) hs[j] = make_float4(0.f, 0.f, 0.f, 0.f);
    {   // preload x for t = 0
        int tg = dir ? (G_ - 1) : 0;
        if (j < 16) xs[j] = ((const float4*)(g_xgrp + (b * G_ + tg) * DTOK))[j];
    }
    __syncthreads();

    for (int t = 0; t < G_; t++) {
        int tg = dir ? (G_ - 1 - t) : t;
        float a1 = bias, a2 = 0.f;
        #pragma unroll
        for (int q = 0; q < 16; q++) {
            float4 x4 = xs[q], h4 = hs[q];
            a1 = fmaf(wi[q].x, x4.x, a1); a1 = fmaf(wi[q].y, x4.y, a1);
            a1 = fmaf(wi[q].z, x4.z, a1); a1 = fmaf(wi[q].w, x4.w, a1);
            a2 = fmaf(wh[q].x, h4.x, a2); a2 = fmaf(wh[q].y, h4.y, a2);
            a2 = fmaf(wh[q].z, h4.z, a2); a2 = fmaf(wh[q].w, h4.w, a2);
        }
        gsm[j] = a1 + a2;
        __syncthreads();
        if (j < 64) {
            float gi = gsm[j], gf = gsm[64 + j], gg = gsm[128 + j], go = gsm[192 + j];
            c = sigp(gf) * c + sigp(gi) * tanhp(gg);
            float h = sigp(go) * tanhp(c);
            ((float*)hs)[j] = h;
            g_hgrp[(b * G_ + tg) * (2 * H_) + dir * H_ + j] = h;
        } else if (j >= 192 && t + 1 < G_) {
            int q = j - 192;
            if (q < 16) {
                int tg2 = dir ? (G_ - 2 - t) : (t + 1);
                xs[q] = ((const float4*)(g_xgrp + (b * G_ + tg2) * DTOK))[q];
            }
        }
        __syncthreads();
    }
}

// ---------------- 5: node gather (sum K groups) + endpoint projections -------
__global__ void k_nodeproj(const int* __restrict__ p2g, const int* __restrict__ idx,
                           const float* __restrict__ wS, const float* __restrict__ bS,
                           const float* __restrict__ wD, const float* __restrict__ bD) {
    int a = blockIdx.x;                       // node 0..2047
    int b = a >> 5, n = a & 31;
    int tid = threadIdx.x;                    // 64
    __shared__ float hrow[2 * H_];
    float s0 = 0.f, s1 = 0.f;
    #pragma unroll
    for (int k = 0; k < K_; k++) {
        int pos = idx[(b * N_ + n) * K_ + k];
        int g   = p2g[b * L_ + pos];
        const float* hp = g_hgrp + (b * G_ + g) * (2 * H_);
        s0 += hp[tid]; s1 += hp[tid + 64];
    }
    hrow[tid] = s0; hrow[tid + 64] = s1;
    __syncthreads();
    const float* w = (tid < 32) ? (wS + tid * 128) : (wD + (tid - 32) * 128);
    float acc = (tid < 32) ? bS[tid] : bD[tid - 32];
    const float4* h4 = (const float4*)hrow;
    #pragma unroll
    for (int q = 0; q < 32; q++) {
        float4 wv = ((const float4*)w)[q];
        float4 hv = h4[q];
        acc = fmaf(wv.x, hv.x, acc); acc = fmaf(wv.y, hv.y, acc);
        acc = fmaf(wv.z, hv.z, acc); acc = fmaf(wv.w, hv.w, acc);
    }
    if (tid < 32) g_rawS[a * NINP + tid] = acc;
    else          g_rawD[a * NINP + tid - 32] = acc;
}

// ---------------- 6: BN stats as count-weighted moments (exact) --------------
__global__ void k_bnstats() {
    int c = blockIdx.x;                       // 0..63 (src 0-31, dst 32-63)
    int tid = threadIdx.x;
    const float* raw = (c < 32) ? g_rawS : g_rawD;
    const int*   cnt = (c < 32) ? g_cntU : g_cntV;
    int cc = c & 31;
    float s = 0.f, s2 = 0.f;
    for (int a = tid; a < NA; a += 256) {
        float w = (float)cnt[a];
        float x = raw[a * NINP + cc];
        s += w * x; s2 += w * x * x;
    }
    __shared__ float r1[256], r2[256];
    r1[tid] = s; r2[tid] = s2; __syncthreads();
    for (int o = 128; o > 0; o >>= 1) {
        if (tid < o) { r1[tid] += r1[tid + o]; r2[tid] += r2[tid + o]; }
        __syncthreads();
    }
    if (tid == 0) {
        float mu  = r1[0] * (1.0f / E_);
        float var = r2[0] * (1.0f / E_) - mu * mu;
        g_bnMu[c] = mu;
        g_bnInv[c] = rsqrtf(var + 1e-5f);
    }
}

// ---------------- 7: normalize tables ----------------
__global__ void k_bnnorm(const float* __restrict__ gS, const float* __restrict__ beS,
                         const float* __restrict__ gD, const float* __restrict__ beD) {
    int t = blockIdx.x * 256 + threadIdx.x;   // 2048*64
    int a = t >> 6, c = t & 63;
    int cc = c & 31;
    if (c < 32) {
        float x = g_rawS[a * NINP + cc];
        g_hsT[a * NINP + cc] = gS[cc] * (x - g_bnMu[c]) * g_bnInv[c] + beS[cc];
    } else {
        float x = g_rawD[a * NINP + cc];
        g_htT[a * NINP + cc] = gD[cc] * (x - g_bnMu[c]) * g_bnInv[c] + beD[cc];
    }
}

// ---------------- 8: exclusive scan of u-histogram (counting sort) ----------
__global__ void k_scan() {
    __shared__ int sums[256];
    int tid = threadIdx.x;
    int loc[8]; int s = 0;
    #pragma unroll
    for (int i = 0; i < 8; i++) { loc[i] = s; s += g_cntU[tid * 8 + i]; }
    sums[tid] = s;
    __syncthreads();
    if (tid == 0) {
        int run = 0;
        for (int i = 0; i < 256; i++) { int tmp = sums[i]; sums[i] = run; run += tmp; }
    }
    __syncthreads();
    int off = sums[tid];
    #pragma unroll
    for (int i = 0; i < 8; i++) {
        int st = off + loc[i];
        g_start[tid * 8 + i] = st;
        g_cursor[tid * 8 + i] = st;
    }
    if (tid == 255) g_start[NA] = E_;
}

// ---------------- 9: scatter edges into u-buckets ----------------
__global__ void k_scatter(const int* __restrict__ u) {
    int e = blockIdx.x * 256 + threadIdx.x;
    int p = atomicAdd(&g_cursor[u[e]], 1);
    g_perm[p] = e;
}

// ---------------- 10: A'[a,rh,j] = hs[a,:]·W[rh,:,j] + v2[rh,j]; C[a,rh] -----
__global__ void __launch_bounds__(256)
k_agemm(const float* __restrict__ W, const float* __restrict__ V,
        const float* __restrict__ Bb) {
    int rh = blockIdx.x;                      // 0..255
    int jj = threadIdx.x & 31, ar = threadIdx.x >> 5;
    float w[32];
    #pragma unroll
    for (int i = 0; i < 32; i++) w[i] = W[rh * 1024 + i * 32 + jj];
    float v2 = V[rh * 64 + 32 + jj];
    float v1 = V[rh * 64 + jj];
    float bb = Bb[rh];
    __shared__ float hsr[8][32];
    int a0beg = blockIdx.y * (NA / 2);
    for (int a0 = a0beg; a0 < a0beg + NA / 2; a0 += 8) {
        hsr[ar][jj] = g_hsT[(a0 + ar) * NINP + jj];
        __syncthreads();
        float acc = v2;
        const float4* hp = (const float4*)hsr[ar];
        #pragma unroll
        for (int q = 0; q < 8; q++) {
            float4 h4 = hp[q];
            acc = fmaf(w[4*q+0], h4.x, acc); acc = fmaf(w[4*q+1], h4.y, acc);
            acc = fmaf(w[4*q+2], h4.z, acc); acc = fmaf(w[4*q+3], h4.w, acc);
        }
        int a = a0 + ar;
        g_Ap[(size_t)a * 8192 + rh * 32 + jj] = acc;
        float part = hsr[ar][jj] * v1;
        #pragma unroll
        for (int o = 16; o > 0; o >>= 1) part += __shfl_xor_sync(0xffffffffu, part, o);
        if (jj == 0) g_C[a * NRH + rh] = part + bb;
        __syncthreads();
    }
}

// ---------------- 11: per-edge dot; z[e,rh]; running z-stats ----------------
__global__ void __launch_bounds__(256)
k_edge(const int* __restrict__ v) {
    int a  = blockIdx.x;                      // u-bucket
    int rh = threadIdx.x;
    float4 areg[8];
    const float4* ap = (const float4*)(g_Ap + (size_t)a * 8192 + rh * 32);
    #pragma unroll
    for (int q = 0; q < 8; q++) areg[q] = ap[q];
    float cinit = g_C[a * NRH + rh];
    int s = g_start[a], eend = g_start[a + 1];
    float s1 = 0.f, s2 = 0.f;
    __shared__ float hts[8][32];
    __shared__ int eid[8];
    for (int p0 = s; p0 < eend; p0 += 8) {
        int nb = min(8, eend - p0);
        if (rh < nb * 32) {
            int g = rh >> 5, lj = rh & 31;
            int e = g_perm[p0 + g];
            if (lj == 0) eid[g] = e;
            hts[g][lj] = g_htT[v[e] * NINP + lj];
        }
        __syncthreads();
        for (int q = 0; q < nb; q++) {
            float acc = cinit;
            const float4* hp = (const float4*)hts[q];
            #pragma unroll
            for (int i = 0; i < 8; i++) {
                float4 h4 = hp[i];
                acc = fmaf(areg[i].x, h4.x, acc); acc = fmaf(areg[i].y, h4.y, acc);
                acc = fmaf(areg[i].z, h4.z, acc); acc = fmaf(areg[i].w, h4.w, acc);
            }
            g_z[(size_t)eid[q] * NRH + rh] = acc;
            s1 += acc; s2 += acc * acc;
        }
        __syncthreads();
    }
    if (eend > s) {
        atomicAdd(&g_zsum[rh], s1);
        atomicAdd(&g_zsq[rh],  s2);
    }
}

// ---------------- 12: finalize z layernorm params ----------------
__global__ void k_zstats(const float* __restrict__ gg, const float* __restrict__ be) {
    int rh = threadIdx.x;
    float mu  = g_zsum[rh] * (1.0f / E_);
    float var = g_zsq[rh] * (1.0f / E_) - mu * mu;
    float inv = rsqrtf(var + 1e-5f);
    float sc  = gg[rh] * inv;
    g_zscale[rh] = sc;
    g_zoff[rh]   = be[rh] - sc * mu;
}

// ---------------- 13: tanh + per-relation reduction -> logits ---------------
__global__ void __launch_bounds__(256)
k_final(const float* __restrict__ uu, float* __restrict__ out) {
    __shared__ float ssc[256], sof[256], su[256];
    int tid = threadIdx.x;
    ssc[tid] = g_zscale[tid]; sof[tid] = g_zoff[tid]; su[tid] = uu[tid];
    __syncthreads();
    int e = blockIdx.x * 256 + tid;
    const float4* zp = (const float4*)(g_z + (size_t)e * NRH);
    float acc[16];
    #pragma unroll
    for (int r = 0; r < 16; r++) acc[r] = 0.f;
    #pragma unroll
    for (int q = 0; q < 64; q++) {
        float4 z4 = zp[q];
        int rh = q * 4;
        int r  = q >> 2;
        acc[r] += su[rh+0] * tanha(fmaf(ssc[rh+0], z4.x, sof[rh+0]));
        acc[r] += su[rh+1] * tanha(fmaf(ssc[rh+1], z4.y, sof[rh+1]));
        acc[r] += su[rh+2] * tanha(fmaf(ssc[rh+2], z4.z, sof[rh+2]));
        acc[r] += su[rh+3] * tanha(fmaf(ssc[rh+3], z4.w, sof[rh+3]));
    }
    float4* op = (float4*)(out + (size_t)e * 16);
    op[0] = make_float4(acc[0],  acc[1],  acc[2],  acc[3]);
    op[1] = make_float4(acc[4],  acc[5],  acc[6],  acc[7]);
    op[2] = make_float4(acc[8],  acc[9],  acc[10], acc[11]);
    op[3] = make_float4(acc[12], acc[13], acc[14], acc[15]);
}

// ---------------- launch ----------------
extern "C" void kernel_launch(void* const* d_in, const int* in_sizes, int n_in,
                              void* d_out, int out_size) {
    const int*   seq  = (const int*)d_in[0];
    const int*   p2g  = (const int*)d_in[1];
    const int*   idx  = (const int*)d_in[2];
    const int*   u    = (const int*)d_in[3];
    const int*   v    = (const int*)d_in[4];
    const float* emb  = (const float*)d_in[5];
    const float* wihF = (const float*)d_in[6];
    const float* whhF = (const float*)d_in[7];
    const float* bihF = (const float*)d_in[8];
    const float* bhhF = (const float*)d_in[9];
    const float* wihB = (const float*)d_in[10];
    const float* whhB = (const float*)d_in[11];
    const float* bihB = (const float*)d_in[12];
    const float* bhhB = (const float*)d_in[13];
    const float* wS   = (const float*)d_in[14];
    const float* bS   = (const float*)d_in[15];
    const float* wD   = (const float*)d_in[16];
    const float* bD   = (const float*)d_in[17];
    const float* gS   = (const float*)d_in[18];
    const float* beS  = (const float*)d_in[19];
    const float* gD   = (const float*)d_in[20];
    const float* beD  = (const float*)d_in[21];
    const float* ntlW = (const float*)d_in[22];
    const float* ntlV = (const float*)d_in[23];
    const float* ntlB = (const float*)d_in[24];
    const float* ntlU = (const float*)d_in[25];
    const float* ntlG = (const float*)d_in[26];
    const float* ntlBe= (const float*)d_in[27];
    float* out = (float*)d_out;

    k_init    <<<8, 256>>>();
    k_embed   <<<64, 256>>>(seq, p2g, emb);
    k_histo   <<<256, 256>>>(u, v);
    k_lstm    <<<128, 256>>>(wihF, whhF, bihF, bhhF, wihB, whhB, bihB, bhhB);
    k_nodeproj<<<2048, 64>>>(p2g, idx, wS, bS, wD, bD);
    k_bnstats <<<64, 256>>>();
    k_bnnorm  <<<512, 256>>>(gS, beS, gD, beD);
    k_scan    <<<1, 256>>>();
    k_scatter <<<256, 256>>>(u);
    k_agemm   <<<dim3(256, 2), 256>>>(ntlW, ntlV, ntlB);
    k_edge    <<<2048, 256>>>(v);
    k_zstats  <<<1, 256>>>(ntlG, ntlBe);
    k_final   <<<256, 256>>>(ntlU, out);
}